// round 10
// baseline (speedup 1.0000x reference)
#include <cuda_runtime.h>
#include <cuda.h>
#include <cuda_bf16.h>
#include <math.h>
#include <stdint.h>

#define NT   16384
#define DIM  2048
#define HID  4096
#define NE   8
#define TK   2
#define NPAIR (NT*TK)
#define NPAD  (NPAIR + NE*256)     // 34816: per-expert 256-padded upper bound
#define NPB   (NPAD/256)           // 136 row blocks (M=256 tiles)

// ---------------- device scratch (no allocations allowed) ----------------
static __device__ __nv_bfloat16 g_w1h[(size_t)NE*HID*DIM];
static __device__ __nv_bfloat16 g_w1l[(size_t)NE*HID*DIM];
static __device__ __nv_bfloat16 g_w2h[(size_t)NE*DIM*HID];
static __device__ __nv_bfloat16 g_w2l[(size_t)NE*DIM*HID];
static __device__ __nv_bfloat16 g_xh[(size_t)NPAD*DIM];
static __device__ __nv_bfloat16 g_xl[(size_t)NPAD*DIM];
static __device__ __nv_bfloat16 g_hh[(size_t)NPAD*HID];
static __device__ __nv_bfloat16 g_hl[(size_t)NPAD*HID];
static __device__ float         g_o [(size_t)NPAD*DIM];
static __device__ int   g_top_idx[NPAIR];
static __device__ float g_top_w[NPAIR];
static __device__ int   g_ppos[NPAIR];
static __device__ int   g_perm[NPAD];
static __device__ int   g_counts[NE];
static __device__ int   g_poff[NE+1];
static __device__ int   g_cursor[NE];
static __device__ float g_probsum[NE];

// ---------------- helpers ----------------
__device__ __forceinline__ uint32_t smem_u32(const void* p) {
    uint32_t a;
    asm("{ .reg .u64 t; cvta.to.shared.u64 t, %1; cvt.u32.u64 %0, t; }" : "=r"(a) : "l"(p));
    return a;
}
// SW64 swizzle (Swizzle<2,4,3>): matches CU_TENSOR_MAP_SWIZZLE_64B
#define SWZ64(o) ((o) ^ (((o) >> 3) & 0x30))

#define LDSM4(r, addr) \
    asm volatile("ldmatrix.sync.aligned.m8n8.x4.shared.b16 {%0,%1,%2,%3}, [%4];" \
        : "=r"((r)[0]), "=r"((r)[1]), "=r"((r)[2]), "=r"((r)[3]) : "r"(addr))

#define MMA_BF16(d, a, bv0, bv1) \
    asm volatile("mma.sync.aligned.m16n8k16.row.col.f32.bf16.bf16.f32 " \
        "{%0,%1,%2,%3}, {%4,%5,%6,%7}, {%8,%9}, {%0,%1,%2,%3};" \
        : "+f"((d)[0]), "+f"((d)[1]), "+f"((d)[2]), "+f"((d)[3]) \
        : "r"((a)[0]), "r"((a)[1]), "r"((a)[2]), "r"((a)[3]), "r"(bv0), "r"(bv1))

#define TMA2D(smem, mapp, cx, cy, mbar) \
    asm volatile("cp.async.bulk.tensor.2d.shared::cta.global.tile.mbarrier::complete_tx::bytes " \
        "[%0], [%1, {%2, %3}], [%4];" \
        :: "r"(smem), "l"(mapp), "r"(cx), "r"(cy), "r"(mbar) : "memory")

#define MB_INIT(a, c) \
    asm volatile("mbarrier.init.shared.b64 [%0], %1;" :: "r"(a), "r"((uint32_t)(c)) : "memory")
#define MB_EXPECT(a, tx) \
    asm volatile("mbarrier.arrive.expect_tx.shared.b64 _, [%0], %1;" :: "r"(a), "r"((uint32_t)(tx)) : "memory")

__device__ __forceinline__ void mb_wait(uint32_t a, uint32_t parity) {
    asm volatile(
        "{\n\t.reg .pred P;\n"
        "W%=:\n\t"
        "mbarrier.try_wait.parity.acquire.cta.shared::cta.b64 P, [%0], %1, 0x989680;\n\t"
        "@P bra D%=;\n\t"
        "bra W%=;\n"
        "D%=:\n\t}"
        :: "r"(a), "r"(parity) : "memory");
}

// ---------------- reset ----------------
__global__ void reset_kernel() {
    int i = threadIdx.x;
    if (i < NE) { g_counts[i] = 0; g_cursor[i] = 0; g_probsum[i] = 0.f; }
}

// ---------------- router ----------------
__global__ __launch_bounds__(256) void router_kernel(const float* __restrict__ x,
                                                     const float* __restrict__ Wr) {
    __shared__ float s_ps[NE];
    __shared__ int   s_ct[NE];
    if (threadIdx.x < NE) { s_ps[threadIdx.x] = 0.f; s_ct[threadIdx.x] = 0; }
    __syncthreads();

    const int lane = threadIdx.x & 31;
    const int t    = blockIdx.x * 8 + (threadIdx.x >> 5);

    float accv[NE];
#pragma unroll
    for (int e = 0; e < NE; e++) accv[e] = 0.f;

    const float4* x4 = (const float4*)(x + (size_t)t * DIM);
    for (int d4 = lane; d4 < DIM / 4; d4 += 32) {
        float4 xv = x4[d4];
        float xs[4] = {xv.x, xv.y, xv.z, xv.w};
#pragma unroll
        for (int r = 0; r < 4; r++) {
            const float4* wr = (const float4*)(Wr + (size_t)(d4 * 4 + r) * NE);
            float4 a = wr[0], b = wr[1];
            accv[0] += xs[r] * a.x; accv[1] += xs[r] * a.y;
            accv[2] += xs[r] * a.z; accv[3] += xs[r] * a.w;
            accv[4] += xs[r] * b.x; accv[5] += xs[r] * b.y;
            accv[6] += xs[r] * b.z; accv[7] += xs[r] * b.w;
        }
    }
#pragma unroll
    for (int e = 0; e < NE; e++) {
#pragma unroll
        for (int o = 16; o > 0; o >>= 1)
            accv[e] += __shfl_down_sync(0xffffffffu, accv[e], o);
    }

    if (lane == 0) {
        float m = accv[0];
#pragma unroll
        for (int e = 1; e < NE; e++) m = fmaxf(m, accv[e]);
        float p[NE]; float s = 0.f;
#pragma unroll
        for (int e = 0; e < NE; e++) { p[e] = expf(accv[e] - m); s += p[e]; }
        float inv = 1.f / s;
#pragma unroll
        for (int e = 0; e < NE; e++) p[e] *= inv;

        int i0 = 0;
#pragma unroll
        for (int e = 1; e < NE; e++) if (p[e] > p[i0]) i0 = e;
        int i1 = (i0 == 0) ? 1 : 0;
#pragma unroll
        for (int e = 0; e < NE; e++) if (e != i0 && p[e] > p[i1]) i1 = e;

        float ws = p[i0] + p[i1];
        g_top_idx[t * 2 + 0] = i0;  g_top_idx[t * 2 + 1] = i1;
        g_top_w[t * 2 + 0] = p[i0] / ws;  g_top_w[t * 2 + 1] = p[i1] / ws;

#pragma unroll
        for (int e = 0; e < NE; e++) atomicAdd(&s_ps[e], p[e]);
        atomicAdd(&s_ct[i0], 1);
        atomicAdd(&s_ct[i1], 1);
    }
    __syncthreads();
    if (threadIdx.x < NE) {
        atomicAdd(&g_probsum[threadIdx.x], s_ps[threadIdx.x]);
        atomicAdd(&g_counts[threadIdx.x],  s_ct[threadIdx.x]);
    }
}

// ---------------- padded prefix offsets (256-multiples for M=256 tiles) ----------------
__global__ void offsets_kernel() {
    if (threadIdx.x == 0) {
        int s = 0;
        for (int e = 0; e < NE; e++) {
            g_poff[e] = s;
            s += ((g_counts[e] + 255) / 256) * 256;
        }
        g_poff[NE] = s;
    }
}

// ---------------- scatter into padded per-expert segments ----------------
__global__ void scatter_kernel() {
    int t = blockIdx.x * blockDim.x + threadIdx.x;
    if (t >= NT) return;
#pragma unroll
    for (int k = 0; k < TK; k++) {
        int e = g_top_idx[t * 2 + k];
        int pos = g_poff[e] + atomicAdd(&g_cursor[e], 1);
        g_perm[pos] = t;
        g_ppos[t * 2 + k] = pos;
    }
}

// ---------------- transpose + bf16 hi/lo split of expert weights ----------------
template<int WHICH>
__global__ void transpose_split_kernel(const float* __restrict__ src) {
    constexpr int R = (WHICH == 1) ? DIM : HID;
    constexpr int C = (WHICH == 1) ? HID : DIM;
    __nv_bfloat16* dh = (WHICH == 1) ? g_w1h : g_w2h;
    __nv_bfloat16* dl = (WHICH == 1) ? g_w1l : g_w2l;

    __shared__ float tile[32][33];
    int e = blockIdx.z;
    const float* s = src + (size_t)e * R * C;
    __nv_bfloat16* ph = dh + (size_t)e * R * C;
    __nv_bfloat16* pl = dl + (size_t)e * R * C;
    int c0 = blockIdx.x * 32, r0 = blockIdx.y * 32;

    for (int i = threadIdx.y; i < 32; i += 8)
        tile[i][threadIdx.x] = s[(size_t)(r0 + i) * C + c0 + threadIdx.x];
    __syncthreads();
    for (int i = threadIdx.y; i < 32; i += 8) {
        float v = tile[threadIdx.x][i];
        __nv_bfloat16 h = __float2bfloat16(v);
        size_t idx = (size_t)(c0 + i) * R + r0 + threadIdx.x;
        ph[idx] = h;
        pl[idx] = __float2bfloat16(v - __bfloat162float(h));
    }
}

// ---------------- gather tokens + bf16 hi/lo split ----------------
__global__ __launch_bounds__(128) void gather_split_kernel(const float* __restrict__ x) {
    int p = blockIdx.x;
    if (p >= g_poff[NE]) return;
    int e = 0;
    while (p >= g_poff[e + 1]) e++;
    int local = p - g_poff[e];
    __nv_bfloat16* ph = g_xh + (size_t)p * DIM;
    __nv_bfloat16* pl = g_xl + (size_t)p * DIM;
    if (local >= g_counts[e]) {
        for (int c = threadIdx.x; c < DIM / 2; c += 128) {
            ((uint32_t*)ph)[c] = 0u;
            ((uint32_t*)pl)[c] = 0u;
        }
        return;
    }
    int tok = g_perm[p];
    const float4* xs = (const float4*)(x + (size_t)tok * DIM);
    for (int c4 = threadIdx.x; c4 < DIM / 4; c4 += 128) {
        float4 v = xs[c4];
        __nv_bfloat16 h0 = __float2bfloat16(v.x), h1 = __float2bfloat16(v.y);
        __nv_bfloat16 h2 = __float2bfloat16(v.z), h3 = __float2bfloat16(v.w);
        ((__nv_bfloat162*)ph)[c4 * 2 + 0] = __halves2bfloat162(h0, h1);
        ((__nv_bfloat162*)ph)[c4 * 2 + 1] = __halves2bfloat162(h2, h3);
        __nv_bfloat16 l0 = __float2bfloat16(v.x - __bfloat162float(h0));
        __nv_bfloat16 l1 = __float2bfloat16(v.y - __bfloat162float(h1));
        __nv_bfloat16 l2 = __float2bfloat16(v.z - __bfloat162float(h2));
        __nv_bfloat16 l3 = __float2bfloat16(v.w - __bfloat162float(h3));
        ((__nv_bfloat162*)pl)[c4 * 2 + 0] = __halves2bfloat162(l0, l1);
        ((__nv_bfloat162*)pl)[c4 * 2 + 1] = __halves2bfloat162(l2, l3);
    }
}

// ---------------- TMA-fed HMMA grouped GEMM ----------------
// CTA tile M=256 x N=128, 512 threads (16 warps, warp tile 32x64).
// K-chunk 32 (64B rows, SW64 via TMA), hi/lo 3-pass, 4-stage mbarrier pipeline.
#define A_PL   16384                 // 256 rows x 64B
#define B_PL   8192                  // 128 rows x 64B
#define STAGE_B (2*A_PL + 2*B_PL)    // 49152
#define NSTG    4
#define SMEM_ASK (1024 + 1024 + NSTG*STAGE_B)

template<int KTOT, int NTOT, bool GELU1>
__global__ __launch_bounds__(512, 1) void gemm_tma(
    const float* __restrict__ bias_base,
    const __grid_constant__ CUtensorMap mAh,
    const __grid_constant__ CUtensorMap mAl,
    const __grid_constant__ CUtensorMap mBh,
    const __grid_constant__ CUtensorMap mBl) {

    const int rowbase = blockIdx.y * 256;
    if (rowbase >= g_poff[NE]) return;
    int e = 0;
    while (rowbase >= g_poff[e + 1]) e++;
    const int colbase = blockIdx.x * 128;
    const int brow = e * NTOT + colbase;
    const int tid = threadIdx.x, wid = tid >> 5, lane = tid & 31;
    const int wm = (wid & 7) * 32, wn = (wid >> 3) * 64;

    extern __shared__ char smem[];
    const uint32_t sb0 = (smem_u32(smem) + 1023) & ~1023u;
    const uint32_t data0 = sb0 + 1024;

    if (tid == 0) {
#pragma unroll
        for (int s = 0; s < NSTG; s++) MB_INIT(sb0 + 8*s, 1);
    }
    __syncthreads();

    auto refill = [&](int kb) {   // load k-block kb into stage kb%NSTG
        const uint32_t st = data0 + (kb & (NSTG-1)) * STAGE_B;
        const uint32_t mbar = sb0 + 8 * (kb & (NSTG-1));
        const int k0 = kb * 32;
        MB_EXPECT(mbar, STAGE_B);
        TMA2D(st,              &mAh, k0, rowbase, mbar);
        TMA2D(st + A_PL,       &mAl, k0, rowbase, mbar);
        TMA2D(st + 2*A_PL,     &mBh, k0, brow,    mbar);
        TMA2D(st + 2*A_PL+B_PL,&mBl, k0, brow,    mbar);
    };

    constexpr int NIT = KTOT / 32;
    if (tid == 0) { refill(0); refill(1); refill(2); }

    float acc[2][8][4];
#pragma unroll
    for (int mt = 0; mt < 2; mt++)
#pragma unroll
        for (int nt = 0; nt < 8; nt++)
#pragma unroll
            for (int r = 0; r < 4; r++) acc[mt][nt][r] = 0.f;

    // per-lane ldmatrix address components (64B rows, SW64)
    const int arow = lane & 15;
    const int akb  = lane >> 4;
    const int nrow = ((lane >> 4) << 3) + (lane & 7);
    const int bkb  = (lane >> 3) & 1;

    for (int it = 0; it < NIT; ++it) {
        // refill stage freed by the sync at the end of iter it-1
        if (tid == 0 && it + 3 < NIT) refill(it + 3);

        const uint32_t base = data0 + (it & (NSTG-1)) * STAGE_B;
        mb_wait(sb0 + 8 * (it & (NSTG-1)), (it >> 2) & 1);

        const uint32_t bAh = base, bAl = base + A_PL;
        const uint32_t bBh = base + 2*A_PL, bBl = base + 2*A_PL + B_PL;

#pragma unroll
        for (int ks = 0; ks < 2; ks++) {
            const int kb0 = ks * 2;
            uint32_t a_hi[2][4], a_lo[2][4];
#pragma unroll
            for (int mt = 0; mt < 2; mt++) {
                uint32_t off = SWZ64((uint32_t)((wm + mt*16 + arow) * 64 + (kb0 + akb) * 16));
                LDSM4(a_hi[mt], bAh + off);
                LDSM4(a_lo[mt], bAl + off);
            }
#pragma unroll
            for (int np = 0; np < 4; np++) {
                uint32_t boff = SWZ64((uint32_t)((wn + np*16 + nrow) * 64 + (kb0 + bkb) * 16));
                uint32_t b_hi[4], b_lo[4];
                LDSM4(b_hi, bBh + boff);
                LDSM4(b_lo, bBl + boff);
#pragma unroll
                for (int mt = 0; mt < 2; mt++) {
                    MMA_BF16(acc[mt][np*2+0], a_hi[mt], b_hi[0], b_hi[1]);
                    MMA_BF16(acc[mt][np*2+1], a_hi[mt], b_hi[2], b_hi[3]);
                }
#pragma unroll
                for (int mt = 0; mt < 2; mt++) {
                    MMA_BF16(acc[mt][np*2+0], a_hi[mt], b_lo[0], b_lo[1]);
                    MMA_BF16(acc[mt][np*2+1], a_hi[mt], b_lo[2], b_lo[3]);
                }
#pragma unroll
                for (int mt = 0; mt < 2; mt++) {
                    MMA_BF16(acc[mt][np*2+0], a_lo[mt], b_hi[0], b_hi[1]);
                    MMA_BF16(acc[mt][np*2+1], a_lo[mt], b_hi[2], b_hi[3]);
                }
            }
        }
        __syncthreads();
    }

    // ---- epilogue ----
    const int gid = lane >> 2, tig = lane & 3;
    const float* bp = bias_base + (size_t)e * NTOT + colbase + wn;

#pragma unroll
    for (int mt = 0; mt < 2; mt++) {
#pragma unroll
        for (int half = 0; half < 2; half++) {
            const int m = rowbase + wm + mt*16 + gid + half*8;
            if (GELU1) {
                __nv_bfloat16* ph = g_hh + (size_t)m * HID + colbase + wn;
                __nv_bfloat16* pl = g_hl + (size_t)m * HID + colbase + wn;
#pragma unroll
                for (int nt = 0; nt < 8; nt++) {
                    int c = nt*8 + tig*2;
                    float v0 = acc[mt][nt][half*2+0] + bp[c];
                    float v1 = acc[mt][nt][half*2+1] + bp[c+1];
                    float gg0 = 0.5f * v0 * (1.f + erff(v0 * 0.70710678118654752440f));
                    float gg1 = 0.5f * v1 * (1.f + erff(v1 * 0.70710678118654752440f));
                    __nv_bfloat16 h0 = __float2bfloat16(gg0);
                    __nv_bfloat16 h1 = __float2bfloat16(gg1);
                    *(__nv_bfloat162*)(ph + c) = __halves2bfloat162(h0, h1);
                    *(__nv_bfloat162*)(pl + c) = __halves2bfloat162(
                        __float2bfloat16(gg0 - __bfloat162float(h0)),
                        __float2bfloat16(gg1 - __bfloat162float(h1)));
                }
            } else {
                float* po = g_o + (size_t)m * DIM + colbase + wn;
#pragma unroll
                for (int nt = 0; nt < 8; nt++) {
                    int c = nt*8 + tig*2;
                    float2 v;
                    v.x = acc[mt][nt][half*2+0] + bp[c];
                    v.y = acc[mt][nt][half*2+1] + bp[c+1];
                    *(float2*)(po + c) = v;
                }
            }
        }
    }
}

// ---------------- combine two expert contributions per token ----------------
__global__ __launch_bounds__(256) void combine_kernel(float* __restrict__ out) {
    size_t id = (size_t)blockIdx.x * 256 + threadIdx.x;
    int t = (int)(id / (DIM / 4));
    int c = (int)(id % (DIM / 4));
    int p0 = g_ppos[t * 2 + 0], p1 = g_ppos[t * 2 + 1];
    float w0 = g_top_w[t * 2 + 0], w1 = g_top_w[t * 2 + 1];
    float4 a = ((const float4*)(g_o + (size_t)p0 * DIM))[c];
    float4 b = ((const float4*)(g_o + (size_t)p1 * DIM))[c];
    float4 r;
    r.x = w0 * a.x + w1 * b.x;
    r.y = w0 * a.y + w1 * b.y;
    r.z = w0 * a.z + w1 * b.z;
    r.w = w0 * a.w + w1 * b.w;
    ((float4*)(out + (size_t)t * DIM))[c] = r;
}

// ---------------- load-balance loss ----------------
__global__ void loss_kernel(float* __restrict__ out, int out_size) {
    if (out_size > NT * DIM) {
        float loss = 0.f;
        for (int e = 0; e < NE; e++)
            loss += (g_probsum[e] / (float)NT) * ((float)g_counts[e] / (float)(NT * TK));
        out[(size_t)NT * DIM] = loss * (float)NE;
    }
}

// ---------------- host: tensor-map construction ----------------
typedef CUresult (*PFN_tmEncode)(CUtensorMap*, CUtensorMapDataType, cuuint32_t, void*,
                                 const cuuint64_t*, const cuuint64_t*, const cuuint32_t*,
                                 const cuuint32_t*, CUtensorMapInterleave, CUtensorMapSwizzle,
                                 CUtensorMapL2promotion, CUtensorMapFloatOOBfill);

static void make_map(PFN_tmEncode enc, CUtensorMap* m, void* base,
                     uint64_t d0, uint64_t d1, uint32_t b0, uint32_t b1) {
    cuuint64_t dims[2]    = {d0, d1};
    cuuint64_t strides[1] = {d0 * 2};
    cuuint32_t box[2]     = {b0, b1};
    cuuint32_t es[2]      = {1, 1};
    enc(m, CU_TENSOR_MAP_DATA_TYPE_BFLOAT16, 2, base, dims, strides, box, es,
        CU_TENSOR_MAP_INTERLEAVE_NONE, CU_TENSOR_MAP_SWIZZLE_64B,
        CU_TENSOR_MAP_L2_PROMOTION_L2_128B, CU_TENSOR_MAP_FLOAT_OOB_FILL_NONE);
}

// ---------------- launch ----------------
extern "C" void kernel_launch(void* const* d_in, const int* in_sizes, int n_in,
                              void* d_out, int out_size) {
    const float* x  = (const float*)d_in[0];
    const float* Wr = (const float*)d_in[1];
    const float* W1 = (const float*)d_in[2];
    const float* b1 = (const float*)d_in[3];
    const float* W2 = (const float*)d_in[4];
    const float* b2 = (const float*)d_in[5];
    float* out = (float*)d_out;

    void* pfn = nullptr;
    cudaDriverEntryPointQueryResult qr;
    cudaGetDriverEntryPoint("cuTensorMapEncodeTiled", &pfn, cudaEnableDefault, &qr);
    PFN_tmEncode enc = (PFN_tmEncode)pfn;

    void *pxh, *pxl, *phh, *phl, *pw1h, *pw1l, *pw2h, *pw2l;
    cudaGetSymbolAddress(&pxh,  g_xh);  cudaGetSymbolAddress(&pxl,  g_xl);
    cudaGetSymbolAddress(&phh,  g_hh);  cudaGetSymbolAddress(&phl,  g_hl);
    cudaGetSymbolAddress(&pw1h, g_w1h); cudaGetSymbolAddress(&pw1l, g_w1l);
    cudaGetSymbolAddress(&pw2h, g_w2h); cudaGetSymbolAddress(&pw2l, g_w2l);

    CUtensorMap mA1h, mA1l, mB1h, mB1l, mA2h, mA2l, mB2h, mB2l;
    make_map(enc, &mA1h, pxh,  DIM, NPAD,             32, 256);
    make_map(enc, &mA1l, pxl,  DIM, NPAD,             32, 256);
    make_map(enc, &mB1h, pw1h, DIM, (uint64_t)NE*HID, 32, 128);
    make_map(enc, &mB1l, pw1l, DIM, (uint64_t)NE*HID, 32, 128);
    make_map(enc, &mA2h, phh,  HID, NPAD,             32, 256);
    make_map(enc, &mA2l, phl,  HID, NPAD,             32, 256);
    make_map(enc, &mB2h, pw2h, HID, (uint64_t)NE*DIM, 32, 128);
    make_map(enc, &mB2l, pw2l, HID, (uint64_t)NE*DIM, 32, 128);

    cudaFuncSetAttribute(gemm_tma<DIM, HID, true>,
                         cudaFuncAttributeMaxDynamicSharedMemorySize, SMEM_ASK);
    cudaFuncSetAttribute(gemm_tma<HID, DIM, false>,
                         cudaFuncAttributeMaxDynamicSharedMemorySize, SMEM_ASK);

    reset_kernel<<<1, 32>>>();
    router_kernel<<<NT / 8, 256>>>(x, Wr);
    offsets_kernel<<<1, 1>>>();
    scatter_kernel<<<(NT + 255) / 256, 256>>>();

    transpose_split_kernel<1><<<dim3(HID / 32, DIM / 32, NE), dim3(32, 8)>>>(W1);
    transpose_split_kernel<2><<<dim3(DIM / 32, HID / 32, NE), dim3(32, 8)>>>(W2);
    gather_split_kernel<<<NPAD, 128>>>(x);

    gemm_tma<DIM, HID, true><<<dim3(HID / 128, NPB), 512, SMEM_ASK>>>(b1, mA1h, mA1l, mB1h, mB1l);
    gemm_tma<HID, DIM, false><<<dim3(DIM / 128, NPB), 512, SMEM_ASK>>>(b2, mA2h, mA2l, mB2h, mB2l);

    combine_kernel<<<(int)((size_t)NT * DIM / 4 / 256), 256>>>(out);
    loss_kernel<<<1, 1>>>(out, out_size);
}

// round 15
// speedup vs baseline: 1.5081x; 1.5081x over previous
#include <cuda_runtime.h>
#include <cuda.h>
#include <cuda_fp16.h>
#include <math.h>
#include <stdint.h>

#define NT   16384
#define DIM  2048
#define HID  4096
#define NE   8
#define TK   2
#define NPAIR (NT*TK)
#define NPAD  (NPAIR + NE*256)     // 34816: per-expert 256-padded upper bound
#define NPB   (NPAD/256)           // 136 row blocks (M=256 tiles)

// ---------------- device scratch (no allocations allowed) ----------------
static __device__ __half g_w1h[(size_t)NE*HID*DIM];   // W1^T, fp16 (single limb)
static __device__ __half g_w2h[(size_t)NE*DIM*HID];   // W2^T, fp16
static __device__ __half g_xh[(size_t)NPAD*DIM];      // gathered x hi limb
static __device__ __half g_xl[(size_t)NPAD*DIM];      // gathered x lo limb
static __device__ __half g_hh[(size_t)NPAD*HID];      // hidden hi limb
static __device__ __half g_hl[(size_t)NPAD*HID];      // hidden lo limb
static __device__ float  g_o [(size_t)NPAD*DIM];
static __device__ int   g_top_idx[NPAIR];
static __device__ float g_top_w[NPAIR];
static __device__ int   g_ppos[NPAIR];
static __device__ int   g_perm[NPAD];
static __device__ int   g_counts[NE];
static __device__ int   g_poff[NE+1];
static __device__ int   g_cursor[NE];
static __device__ float g_probsum[NE];

// ---------------- helpers ----------------
__device__ __forceinline__ uint32_t smem_u32(const void* p) {
    uint32_t a;
    asm("{ .reg .u64 t; cvta.to.shared.u64 t, %1; cvt.u32.u64 %0, t; }" : "=r"(a) : "l"(p));
    return a;
}
#define SWZ128(o) ((o) ^ (((o) >> 3) & 0x70))

#define LDSM4(r, addr) \
    asm volatile("ldmatrix.sync.aligned.m8n8.x4.shared.b16 {%0,%1,%2,%3}, [%4];" \
        : "=r"((r)[0]), "=r"((r)[1]), "=r"((r)[2]), "=r"((r)[3]) : "r"(addr))

#define MMA_F16(d, a, bv0, bv1) \
    asm volatile("mma.sync.aligned.m16n8k16.row.col.f32.f16.f16.f32 " \
        "{%0,%1,%2,%3}, {%4,%5,%6,%7}, {%8,%9}, {%0,%1,%2,%3};" \
        : "+f"((d)[0]), "+f"((d)[1]), "+f"((d)[2]), "+f"((d)[3]) \
        : "r"((a)[0]), "r"((a)[1]), "r"((a)[2]), "r"((a)[3]), "r"(bv0), "r"(bv1))

#define TMA2D(smem, mapp, cx, cy, mbar) \
    asm volatile("cp.async.bulk.tensor.2d.shared::cta.global.tile.mbarrier::complete_tx::bytes " \
        "[%0], [%1, {%2, %3}], [%4];" \
        :: "r"(smem), "l"(mapp), "r"(cx), "r"(cy), "r"(mbar) : "memory")

#define MB_INIT(a, c) \
    asm volatile("mbarrier.init.shared.b64 [%0], %1;" :: "r"(a), "r"((uint32_t)(c)) : "memory")
#define MB_EXPECT(a, tx) \
    asm volatile("mbarrier.arrive.expect_tx.shared.b64 _, [%0], %1;" :: "r"(a), "r"((uint32_t)(tx)) : "memory")

__device__ __forceinline__ void mb_wait(uint32_t a, uint32_t parity) {
    asm volatile(
        "{\n\t.reg .pred P;\n"
        "W%=:\n\t"
        "mbarrier.try_wait.parity.acquire.cta.shared::cta.b64 P, [%0], %1, 0x989680;\n\t"
        "@P bra D%=;\n\t"
        "bra W%=;\n"
        "D%=:\n\t}"
        :: "r"(a), "r"(parity) : "memory");
}

// ---------------- reset ----------------
__global__ void reset_kernel() {
    int i = threadIdx.x;
    if (i < NE) { g_counts[i] = 0; g_cursor[i] = 0; g_probsum[i] = 0.f; }
}

// ---------------- router ----------------
__global__ __launch_bounds__(256) void router_kernel(const float* __restrict__ x,
                                                     const float* __restrict__ Wr) {
    __shared__ float s_ps[NE];
    __shared__ int   s_ct[NE];
    if (threadIdx.x < NE) { s_ps[threadIdx.x] = 0.f; s_ct[threadIdx.x] = 0; }
    __syncthreads();

    const int lane = threadIdx.x & 31;
    const int t    = blockIdx.x * 8 + (threadIdx.x >> 5);

    float accv[NE];
#pragma unroll
    for (int e = 0; e < NE; e++) accv[e] = 0.f;

    const float4* x4 = (const float4*)(x + (size_t)t * DIM);
    for (int d4 = lane; d4 < DIM / 4; d4 += 32) {
        float4 xv = x4[d4];
        float xs[4] = {xv.x, xv.y, xv.z, xv.w};
#pragma unroll
        for (int r = 0; r < 4; r++) {
            const float4* wr = (const float4*)(Wr + (size_t)(d4 * 4 + r) * NE);
            float4 a = wr[0], b = wr[1];
            accv[0] += xs[r] * a.x; accv[1] += xs[r] * a.y;
            accv[2] += xs[r] * a.z; accv[3] += xs[r] * a.w;
            accv[4] += xs[r] * b.x; accv[5] += xs[r] * b.y;
            accv[6] += xs[r] * b.z; accv[7] += xs[r] * b.w;
        }
    }
#pragma unroll
    for (int e = 0; e < NE; e++) {
#pragma unroll
        for (int o = 16; o > 0; o >>= 1)
            accv[e] += __shfl_down_sync(0xffffffffu, accv[e], o);
    }

    if (lane == 0) {
        float m = accv[0];
#pragma unroll
        for (int e = 1; e < NE; e++) m = fmaxf(m, accv[e]);
        float p[NE]; float s = 0.f;
#pragma unroll
        for (int e = 0; e < NE; e++) { p[e] = expf(accv[e] - m); s += p[e]; }
        float inv = 1.f / s;
#pragma unroll
        for (int e = 0; e < NE; e++) p[e] *= inv;

        int i0 = 0;
#pragma unroll
        for (int e = 1; e < NE; e++) if (p[e] > p[i0]) i0 = e;
        int i1 = (i0 == 0) ? 1 : 0;
#pragma unroll
        for (int e = 0; e < NE; e++) if (e != i0 && p[e] > p[i1]) i1 = e;

        float ws = p[i0] + p[i1];
        g_top_idx[t * 2 + 0] = i0;  g_top_idx[t * 2 + 1] = i1;
        g_top_w[t * 2 + 0] = p[i0] / ws;  g_top_w[t * 2 + 1] = p[i1] / ws;

#pragma unroll
        for (int e = 0; e < NE; e++) atomicAdd(&s_ps[e], p[e]);
        atomicAdd(&s_ct[i0], 1);
        atomicAdd(&s_ct[i1], 1);
    }
    __syncthreads();
    if (threadIdx.x < NE) {
        atomicAdd(&g_probsum[threadIdx.x], s_ps[threadIdx.x]);
        atomicAdd(&g_counts[threadIdx.x],  s_ct[threadIdx.x]);
    }
}

// ---------------- padded prefix offsets (256-multiples for M=256 tiles) ----------------
__global__ void offsets_kernel() {
    if (threadIdx.x == 0) {
        int s = 0;
        for (int e = 0; e < NE; e++) {
            g_poff[e] = s;
            s += ((g_counts[e] + 255) / 256) * 256;
        }
        g_poff[NE] = s;
    }
}

// ---------------- scatter into padded per-expert segments ----------------
__global__ void scatter_kernel() {
    int t = blockIdx.x * blockDim.x + threadIdx.x;
    if (t >= NT) return;
#pragma unroll
    for (int k = 0; k < TK; k++) {
        int e = g_top_idx[t * 2 + k];
        int pos = g_poff[e] + atomicAdd(&g_cursor[e], 1);
        g_perm[pos] = t;
        g_ppos[t * 2 + k] = pos;
    }
}

// ---------------- transpose + fp16 round of expert weights (single limb) ----------------
template<int WHICH>   // 1: W1 [DIM][HID] -> [HID][DIM] ; 2: W2 [HID][DIM] -> [DIM][HID]
__global__ void transpose_h_kernel(const float* __restrict__ src) {
    constexpr int R = (WHICH == 1) ? DIM : HID;
    constexpr int C = (WHICH == 1) ? HID : DIM;
    __half* dh = (WHICH == 1) ? g_w1h : g_w2h;

    __shared__ float tile[32][33];
    int e = blockIdx.z;
    const float* s = src + (size_t)e * R * C;
    __half* ph = dh + (size_t)e * R * C;
    int c0 = blockIdx.x * 32, r0 = blockIdx.y * 32;

    for (int i = threadIdx.y; i < 32; i += 8)
        tile[i][threadIdx.x] = s[(size_t)(r0 + i) * C + c0 + threadIdx.x];
    __syncthreads();
    for (int i = threadIdx.y; i < 32; i += 8) {
        float v = tile[threadIdx.x][i];
        ph[(size_t)(c0 + i) * R + r0 + threadIdx.x] = __float2half(v);
    }
}

// ---------------- gather tokens + fp16 Dekker hi/lo split ----------------
__global__ __launch_bounds__(128) void gather_split_kernel(const float* __restrict__ x) {
    int p = blockIdx.x;
    if (p >= g_poff[NE]) return;
    int e = 0;
    while (p >= g_poff[e + 1]) e++;
    int local = p - g_poff[e];
    __half* ph = g_xh + (size_t)p * DIM;
    __half* pl = g_xl + (size_t)p * DIM;
    if (local >= g_counts[e]) {
        for (int c = threadIdx.x; c < DIM / 2; c += 128) {
            ((uint32_t*)ph)[c] = 0u;
            ((uint32_t*)pl)[c] = 0u;
        }
        return;
    }
    int tok = g_perm[p];
    const float4* xs = (const float4*)(x + (size_t)tok * DIM);
    for (int c4 = threadIdx.x; c4 < DIM / 4; c4 += 128) {
        float4 v = xs[c4];
        __half h0 = __float2half(v.x), h1 = __float2half(v.y);
        __half h2 = __float2half(v.z), h3 = __float2half(v.w);
        ((__half2*)ph)[c4 * 2 + 0] = __halves2half2(h0, h1);
        ((__half2*)ph)[c4 * 2 + 1] = __halves2half2(h2, h3);
        __half l0 = __float2half(v.x - __half2float(h0));
        __half l1 = __float2half(v.y - __half2float(h1));
        __half l2 = __float2half(v.z - __half2float(h2));
        __half l3 = __float2half(v.w - __half2float(h3));
        ((__half2*)pl)[c4 * 2 + 0] = __halves2half2(l0, l1);
        ((__half2*)pl)[c4 * 2 + 1] = __halves2half2(l2, l3);
    }
}

// ---------------- TMA-fed HMMA grouped GEMM ----------------
// CTA tile M=256 x N=128, 512 threads (16 warps, warp tile 32x64).
// K-chunk 64 (128B rows, SW128 via TMA), A 2-limb fp16 / B 1-limb fp16 (2 passes),
// 2-stage mbarrier pipeline.
#define A_PL   32768                 // 256 rows x 128B
#define B_PL   16384                 // 128 rows x 128B
#define STAGE_B (2*A_PL + B_PL)      // 81920
#define SMEM_ASK (1024 + 1024 + 2*STAGE_B)

template<int KTOT, int NTOT, bool GELU1>
__global__ __launch_bounds__(512, 1) void gemm_tma(
    const float* __restrict__ bias_base,
    const __grid_constant__ CUtensorMap mAh,
    const __grid_constant__ CUtensorMap mAl,
    const __grid_constant__ CUtensorMap mBh) {

    const int rowbase = blockIdx.y * 256;
    if (rowbase >= g_poff[NE]) return;
    int e = 0;
    while (rowbase >= g_poff[e + 1]) e++;
    const int colbase = blockIdx.x * 128;
    const int brow = e * NTOT + colbase;
    const int tid = threadIdx.x, wid = tid >> 5, lane = tid & 31;
    const int wm = (wid & 7) * 32, wn = (wid >> 3) * 64;

    extern __shared__ char smem[];
    const uint32_t sb0 = (smem_u32(smem) + 1023) & ~1023u;
    const uint32_t mb0 = sb0, mb1 = sb0 + 8;
    const uint32_t data0 = sb0 + 1024;

    if (tid == 0) { MB_INIT(mb0, 1); MB_INIT(mb1, 1); }
    __syncthreads();

    constexpr int NIT = KTOT / 64;
    if (tid == 0) {
        MB_EXPECT(mb0, STAGE_B);
        TMA2D(data0,          &mAh, 0, rowbase, mb0);
        TMA2D(data0 + A_PL,   &mAl, 0, rowbase, mb0);
        TMA2D(data0 + 2*A_PL, &mBh, 0, brow,    mb0);
        MB_EXPECT(mb1, STAGE_B);
        uint32_t d1 = data0 + STAGE_B;
        TMA2D(d1,          &mAh, 64, rowbase, mb1);
        TMA2D(d1 + A_PL,   &mAl, 64, rowbase, mb1);
        TMA2D(d1 + 2*A_PL, &mBh, 64, brow,    mb1);
    }

    float acc[2][8][4];
#pragma unroll
    for (int mt = 0; mt < 2; mt++)
#pragma unroll
        for (int nt = 0; nt < 8; nt++)
#pragma unroll
            for (int r = 0; r < 4; r++) acc[mt][nt][r] = 0.f;

    // per-lane ldmatrix address components
    const int arow = lane & 15;
    const int akb  = lane >> 4;
    const int nrow = ((lane >> 4) << 3) + (lane & 7);
    const int bkb  = (lane >> 3) & 1;

    for (int it = 0; it < NIT; ++it) {
        const int b = it & 1;
        const uint32_t base = data0 + b * STAGE_B;
        const uint32_t mbar = b ? mb1 : mb0;
        mb_wait(mbar, (it >> 1) & 1);

        const uint32_t bAh = base, bAl = base + A_PL, bBh = base + 2*A_PL;

#pragma unroll
        for (int ks = 0; ks < 4; ks++) {
            const int kb0 = ks * 2;
            uint32_t a_hi[2][4], a_lo[2][4];
#pragma unroll
            for (int mt = 0; mt < 2; mt++) {
                uint32_t off = SWZ128((uint32_t)((wm + mt*16 + arow) * 128 + (kb0 + akb) * 16));
                LDSM4(a_hi[mt], bAh + off);
                LDSM4(a_lo[mt], bAl + off);
            }
#pragma unroll
            for (int np = 0; np < 4; np++) {
                uint32_t boff = SWZ128((uint32_t)((wn + np*16 + nrow) * 128 + (kb0 + bkb) * 16));
                uint32_t b_hi[4];
                LDSM4(b_hi, bBh + boff);
#pragma unroll
                for (int mt = 0; mt < 2; mt++) {
                    MMA_F16(acc[mt][np*2+0], a_hi[mt], b_hi[0], b_hi[1]);
                    MMA_F16(acc[mt][np*2+1], a_hi[mt], b_hi[2], b_hi[3]);
                }
#pragma unroll
                for (int mt = 0; mt < 2; mt++) {
                    MMA_F16(acc[mt][np*2+0], a_lo[mt], b_hi[0], b_hi[1]);
                    MMA_F16(acc[mt][np*2+1], a_lo[mt], b_hi[2], b_hi[3]);
                }
            }
        }
        __syncthreads();
        if (it + 2 < NIT && tid == 0) {
            MB_EXPECT(mbar, STAGE_B);
            int k0 = (it + 2) * 64;
            TMA2D(base,          &mAh, k0, rowbase, mbar);
            TMA2D(base + A_PL,   &mAl, k0, rowbase, mbar);
            TMA2D(base + 2*A_PL, &mBh, k0, brow,    mbar);
        }
    }

    // ---- epilogue ----
    const int gid = lane >> 2, tig = lane & 3;
    const float* bp = bias_base + (size_t)e * NTOT + colbase + wn;

#pragma unroll
    for (int mt = 0; mt < 2; mt++) {
#pragma unroll
        for (int half = 0; half < 2; half++) {
            const int m = rowbase + wm + mt*16 + gid + half*8;
            if (GELU1) {
                __half* ph = g_hh + (size_t)m * HID + colbase + wn;
                __half* pl = g_hl + (size_t)m * HID + colbase + wn;
#pragma unroll
                for (int nt = 0; nt < 8; nt++) {
                    int c = nt*8 + tig*2;
                    float v0 = acc[mt][nt][half*2+0] + bp[c];
                    float v1 = acc[mt][nt][half*2+1] + bp[c+1];
                    float gg0 = 0.5f * v0 * (1.f + erff(v0 * 0.70710678118654752440f));
                    float gg1 = 0.5f * v1 * (1.f + erff(v1 * 0.70710678118654752440f));
                    __half h0 = __float2half(gg0);
                    __half h1 = __float2half(gg1);
                    *(__half2*)(ph + c) = __halves2half2(h0, h1);
                    *(__half2*)(pl + c) = __halves2half2(
                        __float2half(gg0 - __half2float(h0)),
                        __float2half(gg1 - __half2float(h1)));
                }
            } else {
                float* po = g_o + (size_t)m * DIM + colbase + wn;
#pragma unroll
                for (int nt = 0; nt < 8; nt++) {
                    int c = nt*8 + tig*2;
                    float2 v;
                    v.x = acc[mt][nt][half*2+0] + bp[c];
                    v.y = acc[mt][nt][half*2+1] + bp[c+1];
                    *(float2*)(po + c) = v;
                }
            }
        }
    }
}

// ---------------- combine two expert contributions per token ----------------
__global__ __launch_bounds__(256) void combine_kernel(float* __restrict__ out) {
    size_t id = (size_t)blockIdx.x * 256 + threadIdx.x;
    int t = (int)(id / (DIM / 4));
    int c = (int)(id % (DIM / 4));
    int p0 = g_ppos[t * 2 + 0], p1 = g_ppos[t * 2 + 1];
    float w0 = g_top_w[t * 2 + 0], w1 = g_top_w[t * 2 + 1];
    float4 a = ((const float4*)(g_o + (size_t)p0 * DIM))[c];
    float4 b = ((const float4*)(g_o + (size_t)p1 * DIM))[c];
    float4 r;
    r.x = w0 * a.x + w1 * b.x;
    r.y = w0 * a.y + w1 * b.y;
    r.z = w0 * a.z + w1 * b.z;
    r.w = w0 * a.w + w1 * b.w;
    ((float4*)(out + (size_t)t * DIM))[c] = r;
}

// ---------------- load-balance loss ----------------
__global__ void loss_kernel(float* __restrict__ out, int out_size) {
    if (out_size > NT * DIM) {
        float loss = 0.f;
        for (int e = 0; e < NE; e++)
            loss += (g_probsum[e] / (float)NT) * ((float)g_counts[e] / (float)(NT * TK));
        out[(size_t)NT * DIM] = loss * (float)NE;
    }
}

// ---------------- host: tensor-map construction ----------------
typedef CUresult (*PFN_tmEncode)(CUtensorMap*, CUtensorMapDataType, cuuint32_t, void*,
                                 const cuuint64_t*, const cuuint64_t*, const cuuint32_t*,
                                 const cuuint32_t*, CUtensorMapInterleave, CUtensorMapSwizzle,
                                 CUtensorMapL2promotion, CUtensorMapFloatOOBfill);

static void make_map(PFN_tmEncode enc, CUtensorMap* m, void* base,
                     uint64_t d0, uint64_t d1, uint32_t b0, uint32_t b1) {
    cuuint64_t dims[2]    = {d0, d1};
    cuuint64_t strides[1] = {d0 * 2};
    cuuint32_t box[2]     = {b0, b1};
    cuuint32_t es[2]      = {1, 1};
    enc(m, CU_TENSOR_MAP_DATA_TYPE_FLOAT16, 2, base, dims, strides, box, es,
        CU_TENSOR_MAP_INTERLEAVE_NONE, CU_TENSOR_MAP_SWIZZLE_128B,
        CU_TENSOR_MAP_L2_PROMOTION_L2_128B, CU_TENSOR_MAP_FLOAT_OOB_FILL_NONE);
}

// ---------------- launch ----------------
extern "C" void kernel_launch(void* const* d_in, const int* in_sizes, int n_in,
                              void* d_out, int out_size) {
    const float* x  = (const float*)d_in[0];
    const float* Wr = (const float*)d_in[1];
    const float* W1 = (const float*)d_in[2];
    const float* b1 = (const float*)d_in[3];
    const float* W2 = (const float*)d_in[4];
    const float* b2 = (const float*)d_in[5];
    float* out = (float*)d_out;

    void* pfn = nullptr;
    cudaDriverEntryPointQueryResult qr;
    cudaGetDriverEntryPoint("cuTensorMapEncodeTiled", &pfn, cudaEnableDefault, &qr);
    PFN_tmEncode enc = (PFN_tmEncode)pfn;

    void *pxh, *pxl, *phh, *phl, *pw1h, *pw2h;
    cudaGetSymbolAddress(&pxh,  g_xh);  cudaGetSymbolAddress(&pxl,  g_xl);
    cudaGetSymbolAddress(&phh,  g_hh);  cudaGetSymbolAddress(&phl,  g_hl);
    cudaGetSymbolAddress(&pw1h, g_w1h); cudaGetSymbolAddress(&pw2h, g_w2h);

    CUtensorMap mA1h, mA1l, mB1h, mA2h, mA2l, mB2h;
    make_map(enc, &mA1h, pxh,  DIM, NPAD,             64, 256);
    make_map(enc, &mA1l, pxl,  DIM, NPAD,             64, 256);
    make_map(enc, &mB1h, pw1h, DIM, (uint64_t)NE*HID, 64, 128);
    make_map(enc, &mA2h, phh,  HID, NPAD,             64, 256);
    make_map(enc, &mA2l, phl,  HID, NPAD,             64, 256);
    make_map(enc, &mB2h, pw2h, HID, (uint64_t)NE*DIM, 64, 128);

    cudaFuncSetAttribute(gemm_tma<DIM, HID, true>,
                         cudaFuncAttributeMaxDynamicSharedMemorySize, SMEM_ASK);
    cudaFuncSetAttribute(gemm_tma<HID, DIM, false>,
                         cudaFuncAttributeMaxDynamicSharedMemorySize, SMEM_ASK);

    reset_kernel<<<1, 32>>>();
    router_kernel<<<NT / 8, 256>>>(x, Wr);
    offsets_kernel<<<1, 1>>>();
    scatter_kernel<<<(NT + 255) / 256, 256>>>();

    transpose_h_kernel<1><<<dim3(HID / 32, DIM / 32, NE), dim3(32, 8)>>>(W1);
    transpose_h_kernel<2><<<dim3(DIM / 32, HID / 32, NE), dim3(32, 8)>>>(W2);
    gather_split_kernel<<<NPAD, 128>>>(x);

    gemm_tma<DIM, HID, true><<<dim3(HID / 128, NPB), 512, SMEM_ASK>>>(b1, mA1h, mA1l, mB1h);
    gemm_tma<HID, DIM, false><<<dim3(DIM / 128, NPB), 512, SMEM_ASK>>>(b2, mA2h, mA2l, mB2h);

    combine_kernel<<<(int)((size_t)NT * DIM / 4 / 256), 256>>>(out);
    loss_kernel<<<1, 1>>>(out, out_size);
}

// round 16
// speedup vs baseline: 2.4640x; 1.6338x over previous
#include <cuda_runtime.h>
#include <cuda.h>
#include <cuda_fp16.h>
#include <math.h>
#include <stdint.h>

#define NT   16384
#define DIM  2048
#define HID  4096
#define NE   8
#define TK   2
#define NPAIR (NT*TK)
#define NPAD  (NPAIR + NE*256)     // 34816: per-expert 256-padded upper bound
#define NPB   (NPAD/256)           // 136 row blocks (M=256 tiles)

// ---------------- device scratch (no allocations allowed) ----------------
static __device__ __half g_w1h[(size_t)NE*HID*DIM];   // W1^T, fp16
static __device__ __half g_w2h[(size_t)NE*DIM*HID];   // W2^T, fp16
static __device__ __half g_xh[(size_t)NPAD*DIM];      // gathered x, fp16
static __device__ __half g_hh[(size_t)NPAD*HID];      // hidden, fp16
static __device__ float  g_o [(size_t)NPAD*DIM];
static __device__ int   g_top_idx[NPAIR];
static __device__ float g_top_w[NPAIR];
static __device__ int   g_ppos[NPAIR];
static __device__ int   g_perm[NPAD];
static __device__ int   g_counts[NE];
static __device__ int   g_poff[NE+1];
static __device__ int   g_cursor[NE];
static __device__ float g_probsum[NE];

// ---------------- helpers ----------------
__device__ __forceinline__ uint32_t smem_u32(const void* p) {
    uint32_t a;
    asm("{ .reg .u64 t; cvta.to.shared.u64 t, %1; cvt.u32.u64 %0, t; }" : "=r"(a) : "l"(p));
    return a;
}
#define SWZ128(o) ((o) ^ (((o) >> 3) & 0x70))

#define LDSM4(r, addr) \
    asm volatile("ldmatrix.sync.aligned.m8n8.x4.shared.b16 {%0,%1,%2,%3}, [%4];" \
        : "=r"((r)[0]), "=r"((r)[1]), "=r"((r)[2]), "=r"((r)[3]) : "r"(addr))

#define MMA_F16(d, a, bv0, bv1) \
    asm volatile("mma.sync.aligned.m16n8k16.row.col.f32.f16.f16.f32 " \
        "{%0,%1,%2,%3}, {%4,%5,%6,%7}, {%8,%9}, {%0,%1,%2,%3};" \
        : "+f"((d)[0]), "+f"((d)[1]), "+f"((d)[2]), "+f"((d)[3]) \
        : "r"((a)[0]), "r"((a)[1]), "r"((a)[2]), "r"((a)[3]), "r"(bv0), "r"(bv1))

#define TMA2D(smem, mapp, cx, cy, mbar) \
    asm volatile("cp.async.bulk.tensor.2d.shared::cta.global.tile.mbarrier::complete_tx::bytes " \
        "[%0], [%1, {%2, %3}], [%4];" \
        :: "r"(smem), "l"(mapp), "r"(cx), "r"(cy), "r"(mbar) : "memory")

#define MB_INIT(a, c) \
    asm volatile("mbarrier.init.shared.b64 [%0], %1;" :: "r"(a), "r"((uint32_t)(c)) : "memory")
#define MB_EXPECT(a, tx) \
    asm volatile("mbarrier.arrive.expect_tx.shared.b64 _, [%0], %1;" :: "r"(a), "r"((uint32_t)(tx)) : "memory")

__device__ __forceinline__ void mb_wait(uint32_t a, uint32_t parity) {
    asm volatile(
        "{\n\t.reg .pred P;\n"
        "W%=:\n\t"
        "mbarrier.try_wait.parity.acquire.cta.shared::cta.b64 P, [%0], %1, 0x989680;\n\t"
        "@P bra D%=;\n\t"
        "bra W%=;\n"
        "D%=:\n\t}"
        :: "r"(a), "r"(parity) : "memory");
}

// ---------------- reset ----------------
__global__ void reset_kernel() {
    int i = threadIdx.x;
    if (i < NE) { g_counts[i] = 0; g_cursor[i] = 0; g_probsum[i] = 0.f; }
}

// ---------------- router ----------------
__global__ __launch_bounds__(256) void router_kernel(const float* __restrict__ x,
                                                     const float* __restrict__ Wr) {
    __shared__ float s_ps[NE];
    __shared__ int   s_ct[NE];
    if (threadIdx.x < NE) { s_ps[threadIdx.x] = 0.f; s_ct[threadIdx.x] = 0; }
    __syncthreads();

    const int lane = threadIdx.x & 31;
    const int t    = blockIdx.x * 8 + (threadIdx.x >> 5);

    float accv[NE];
#pragma unroll
    for (int e = 0; e < NE; e++) accv[e] = 0.f;

    const float4* x4 = (const float4*)(x + (size_t)t * DIM);
    for (int d4 = lane; d4 < DIM / 4; d4 += 32) {
        float4 xv = x4[d4];
        float xs[4] = {xv.x, xv.y, xv.z, xv.w};
#pragma unroll
        for (int r = 0; r < 4; r++) {
            const float4* wr = (const float4*)(Wr + (size_t)(d4 * 4 + r) * NE);
            float4 a = wr[0], b = wr[1];
            accv[0] += xs[r] * a.x; accv[1] += xs[r] * a.y;
            accv[2] += xs[r] * a.z; accv[3] += xs[r] * a.w;
            accv[4] += xs[r] * b.x; accv[5] += xs[r] * b.y;
            accv[6] += xs[r] * b.z; accv[7] += xs[r] * b.w;
        }
    }
#pragma unroll
    for (int e = 0; e < NE; e++) {
#pragma unroll
        for (int o = 16; o > 0; o >>= 1)
            accv[e] += __shfl_down_sync(0xffffffffu, accv[e], o);
    }

    if (lane == 0) {
        float m = accv[0];
#pragma unroll
        for (int e = 1; e < NE; e++) m = fmaxf(m, accv[e]);
        float p[NE]; float s = 0.f;
#pragma unroll
        for (int e = 0; e < NE; e++) { p[e] = expf(accv[e] - m); s += p[e]; }
        float inv = 1.f / s;
#pragma unroll
        for (int e = 0; e < NE; e++) p[e] *= inv;

        int i0 = 0;
#pragma unroll
        for (int e = 1; e < NE; e++) if (p[e] > p[i0]) i0 = e;
        int i1 = (i0 == 0) ? 1 : 0;
#pragma unroll
        for (int e = 0; e < NE; e++) if (e != i0 && p[e] > p[i1]) i1 = e;

        float ws = p[i0] + p[i1];
        g_top_idx[t * 2 + 0] = i0;  g_top_idx[t * 2 + 1] = i1;
        g_top_w[t * 2 + 0] = p[i0] / ws;  g_top_w[t * 2 + 1] = p[i1] / ws;

#pragma unroll
        for (int e = 0; e < NE; e++) atomicAdd(&s_ps[e], p[e]);
        atomicAdd(&s_ct[i0], 1);
        atomicAdd(&s_ct[i1], 1);
    }
    __syncthreads();
    if (threadIdx.x < NE) {
        atomicAdd(&g_probsum[threadIdx.x], s_ps[threadIdx.x]);
        atomicAdd(&g_counts[threadIdx.x],  s_ct[threadIdx.x]);
    }
}

// ---------------- padded prefix offsets (256-multiples for M=256 tiles) ----------------
__global__ void offsets_kernel() {
    if (threadIdx.x == 0) {
        int s = 0;
        for (int e = 0; e < NE; e++) {
            g_poff[e] = s;
            s += ((g_counts[e] + 255) / 256) * 256;
        }
        g_poff[NE] = s;
    }
}

// ---------------- scatter into padded per-expert segments ----------------
__global__ void scatter_kernel() {
    int t = blockIdx.x * blockDim.x + threadIdx.x;
    if (t >= NT) return;
#pragma unroll
    for (int k = 0; k < TK; k++) {
        int e = g_top_idx[t * 2 + k];
        int pos = g_poff[e] + atomicAdd(&g_cursor[e], 1);
        g_perm[pos] = t;
        g_ppos[t * 2 + k] = pos;
    }
}

// ---------------- transpose + fp16 round of expert weights ----------------
template<int WHICH>   // 1: W1 [DIM][HID] -> [HID][DIM] ; 2: W2 [HID][DIM] -> [DIM][HID]
__global__ void transpose_h_kernel(const float* __restrict__ src) {
    constexpr int R = (WHICH == 1) ? DIM : HID;
    constexpr int C = (WHICH == 1) ? HID : DIM;
    __half* dh = (WHICH == 1) ? g_w1h : g_w2h;

    __shared__ float tile[32][33];
    int e = blockIdx.z;
    const float* s = src + (size_t)e * R * C;
    __half* ph = dh + (size_t)e * R * C;
    int c0 = blockIdx.x * 32, r0 = blockIdx.y * 32;

    for (int i = threadIdx.y; i < 32; i += 8)
        tile[i][threadIdx.x] = s[(size_t)(r0 + i) * C + c0 + threadIdx.x];
    __syncthreads();
    for (int i = threadIdx.y; i < 32; i += 8) {
        float v = tile[threadIdx.x][i];
        ph[(size_t)(c0 + i) * R + r0 + threadIdx.x] = __float2half(v);
    }
}

// ---------------- gather tokens + fp16 round ----------------
__global__ __launch_bounds__(128) void gather_h_kernel(const float* __restrict__ x) {
    int p = blockIdx.x;
    if (p >= g_poff[NE]) return;
    int e = 0;
    while (p >= g_poff[e + 1]) e++;
    int local = p - g_poff[e];
    __half* ph = g_xh + (size_t)p * DIM;
    if (local >= g_counts[e]) {
        for (int c = threadIdx.x; c < DIM / 2; c += 128)
            ((uint32_t*)ph)[c] = 0u;
        return;
    }
    int tok = g_perm[p];
    const float4* xs = (const float4*)(x + (size_t)tok * DIM);
    for (int c4 = threadIdx.x; c4 < DIM / 4; c4 += 128) {
        float4 v = xs[c4];
        ((__half2*)ph)[c4 * 2 + 0] = __halves2half2(__float2half(v.x), __float2half(v.y));
        ((__half2*)ph)[c4 * 2 + 1] = __halves2half2(__float2half(v.z), __float2half(v.w));
    }
}

// ---------------- TMA-fed HMMA grouped GEMM (single-pass fp16) ----------------
// CTA tile M=256 x N=128, 512 threads (16 warps, warp tile 32x64).
// K-chunk 64 (128B rows, SW128 via TMA), 3-stage mbarrier pipeline.
#define A_PL   32768                 // 256 rows x 128B
#define B_PL   16384                 // 128 rows x 128B
#define STAGE_B (A_PL + B_PL)        // 49152
#define NSTG    3
#define SMEM_ASK (1024 + 1024 + NSTG*STAGE_B)

template<int KTOT, int NTOT, bool GELU1>
__global__ __launch_bounds__(512, 1) void gemm_tma(
    const float* __restrict__ bias_base,
    const __grid_constant__ CUtensorMap mAh,
    const __grid_constant__ CUtensorMap mBh) {

    const int rowbase = blockIdx.y * 256;
    if (rowbase >= g_poff[NE]) return;
    int e = 0;
    while (rowbase >= g_poff[e + 1]) e++;
    const int colbase = blockIdx.x * 128;
    const int brow = e * NTOT + colbase;
    const int tid = threadIdx.x, wid = tid >> 5, lane = tid & 31;
    const int wm = (wid & 7) * 32, wn = (wid >> 3) * 64;

    extern __shared__ char smem[];
    const uint32_t sb0 = (smem_u32(smem) + 1023) & ~1023u;
    const uint32_t data0 = sb0 + 1024;

    if (tid == 0) {
#pragma unroll
        for (int s = 0; s < NSTG; s++) MB_INIT(sb0 + 8*s, 1);
    }
    __syncthreads();

    auto refill = [&](int kb, int stg) {
        const uint32_t st = data0 + stg * STAGE_B;
        const uint32_t mbar = sb0 + 8 * stg;
        const int k0 = kb * 64;
        MB_EXPECT(mbar, STAGE_B);
        TMA2D(st,        &mAh, k0, rowbase, mbar);
        TMA2D(st + A_PL, &mBh, k0, brow,    mbar);
    };

    constexpr int NIT = KTOT / 64;
    if (tid == 0) { refill(0, 0); refill(1, 1); refill(2, 2); }

    float acc[2][8][4];
#pragma unroll
    for (int mt = 0; mt < 2; mt++)
#pragma unroll
        for (int nt = 0; nt < 8; nt++)
#pragma unroll
            for (int r = 0; r < 4; r++) acc[mt][nt][r] = 0.f;

    // per-lane ldmatrix address components
    const int arow = lane & 15;
    const int akb  = lane >> 4;
    const int nrow = ((lane >> 4) << 3) + (lane & 7);
    const int bkb  = (lane >> 3) & 1;

    int stg = 0, par = 0;
    for (int it = 0; it < NIT; ++it) {
        const uint32_t base = data0 + stg * STAGE_B;
        mb_wait(sb0 + 8 * stg, par);

        const uint32_t bAh = base, bBh = base + A_PL;

#pragma unroll
        for (int ks = 0; ks < 4; ks++) {
            const int kb0 = ks * 2;
            uint32_t a_hi[2][4];
#pragma unroll
            for (int mt = 0; mt < 2; mt++) {
                uint32_t off = SWZ128((uint32_t)((wm + mt*16 + arow) * 128 + (kb0 + akb) * 16));
                LDSM4(a_hi[mt], bAh + off);
            }
#pragma unroll
            for (int np = 0; np < 4; np++) {
                uint32_t boff = SWZ128((uint32_t)((wn + np*16 + nrow) * 128 + (kb0 + bkb) * 16));
                uint32_t b_hi[4];
                LDSM4(b_hi, bBh + boff);
#pragma unroll
                for (int mt = 0; mt < 2; mt++) {
                    MMA_F16(acc[mt][np*2+0], a_hi[mt], b_hi[0], b_hi[1]);
                    MMA_F16(acc[mt][np*2+1], a_hi[mt], b_hi[2], b_hi[3]);
                }
            }
        }
        __syncthreads();
        if (it + 3 < NIT && tid == 0) refill(it + 3, stg);
        if (++stg == NSTG) { stg = 0; par ^= 1; }
    }

    // ---- epilogue ----
    const int gid = lane >> 2, tig = lane & 3;
    const float* bp = bias_base + (size_t)e * NTOT + colbase + wn;

#pragma unroll
    for (int mt = 0; mt < 2; mt++) {
#pragma unroll
        for (int half = 0; half < 2; half++) {
            const int m = rowbase + wm + mt*16 + gid + half*8;
            if (GELU1) {
                __half* ph = g_hh + (size_t)m * HID + colbase + wn;
#pragma unroll
                for (int nt = 0; nt < 8; nt++) {
                    int c = nt*8 + tig*2;
                    float v0 = acc[mt][nt][half*2+0] + bp[c];
                    float v1 = acc[mt][nt][half*2+1] + bp[c+1];
                    float gg0 = 0.5f * v0 * (1.f + erff(v0 * 0.70710678118654752440f));
                    float gg1 = 0.5f * v1 * (1.f + erff(v1 * 0.70710678118654752440f));
                    *(__half2*)(ph + c) = __halves2half2(__float2half(gg0), __float2half(gg1));
                }
            } else {
                float* po = g_o + (size_t)m * DIM + colbase + wn;
#pragma unroll
                for (int nt = 0; nt < 8; nt++) {
                    int c = nt*8 + tig*2;
                    float2 v;
                    v.x = acc[mt][nt][half*2+0] + bp[c];
                    v.y = acc[mt][nt][half*2+1] + bp[c+1];
                    *(float2*)(po + c) = v;
                }
            }
        }
    }
}

// ---------------- combine two expert contributions per token ----------------
__global__ __launch_bounds__(256) void combine_kernel(float* __restrict__ out) {
    size_t id = (size_t)blockIdx.x * 256 + threadIdx.x;
    int t = (int)(id / (DIM / 4));
    int c = (int)(id % (DIM / 4));
    int p0 = g_ppos[t * 2 + 0], p1 = g_ppos[t * 2 + 1];
    float w0 = g_top_w[t * 2 + 0], w1 = g_top_w[t * 2 + 1];
    float4 a = ((const float4*)(g_o + (size_t)p0 * DIM))[c];
    float4 b = ((const float4*)(g_o + (size_t)p1 * DIM))[c];
    float4 r;
    r.x = w0 * a.x + w1 * b.x;
    r.y = w0 * a.y + w1 * b.y;
    r.z = w0 * a.z + w1 * b.z;
    r.w = w0 * a.w + w1 * b.w;
    ((float4*)(out + (size_t)t * DIM))[c] = r;
}

// ---------------- load-balance loss ----------------
__global__ void loss_kernel(float* __restrict__ out, int out_size) {
    if (out_size > NT * DIM) {
        float loss = 0.f;
        for (int e = 0; e < NE; e++)
            loss += (g_probsum[e] / (float)NT) * ((float)g_counts[e] / (float)(NT * TK));
        out[(size_t)NT * DIM] = loss * (float)NE;
    }
}

// ---------------- host: tensor-map construction ----------------
typedef CUresult (*PFN_tmEncode)(CUtensorMap*, CUtensorMapDataType, cuuint32_t, void*,
                                 const cuuint64_t*, const cuuint64_t*, const cuuint32_t*,
                                 const cuuint32_t*, CUtensorMapInterleave, CUtensorMapSwizzle,
                                 CUtensorMapL2promotion, CUtensorMapFloatOOBfill);

static void make_map(PFN_tmEncode enc, CUtensorMap* m, void* base,
                     uint64_t d0, uint64_t d1, uint32_t b0, uint32_t b1) {
    cuuint64_t dims[2]    = {d0, d1};
    cuuint64_t strides[1] = {d0 * 2};
    cuuint32_t box[2]     = {b0, b1};
    cuuint32_t es[2]      = {1, 1};
    enc(m, CU_TENSOR_MAP_DATA_TYPE_FLOAT16, 2, base, dims, strides, box, es,
        CU_TENSOR_MAP_INTERLEAVE_NONE, CU_TENSOR_MAP_SWIZZLE_128B,
        CU_TENSOR_MAP_L2_PROMOTION_L2_128B, CU_TENSOR_MAP_FLOAT_OOB_FILL_NONE);
}

// ---------------- launch ----------------
extern "C" void kernel_launch(void* const* d_in, const int* in_sizes, int n_in,
                              void* d_out, int out_size) {
    const float* x  = (const float*)d_in[0];
    const float* Wr = (const float*)d_in[1];
    const float* W1 = (const float*)d_in[2];
    const float* b1 = (const float*)d_in[3];
    const float* W2 = (const float*)d_in[4];
    const float* b2 = (const float*)d_in[5];
    float* out = (float*)d_out;

    void* pfn = nullptr;
    cudaDriverEntryPointQueryResult qr;
    cudaGetDriverEntryPoint("cuTensorMapEncodeTiled", &pfn, cudaEnableDefault, &qr);
    PFN_tmEncode enc = (PFN_tmEncode)pfn;

    void *pxh, *phh, *pw1h, *pw2h;
    cudaGetSymbolAddress(&pxh,  g_xh);
    cudaGetSymbolAddress(&phh,  g_hh);
    cudaGetSymbolAddress(&pw1h, g_w1h); cudaGetSymbolAddress(&pw2h, g_w2h);

    CUtensorMap mA1h, mB1h, mA2h, mB2h;
    make_map(enc, &mA1h, pxh,  DIM, NPAD,             64, 256);
    make_map(enc, &mB1h, pw1h, DIM, (uint64_t)NE*HID, 64, 128);
    make_map(enc, &mA2h, phh,  HID, NPAD,             64, 256);
    make_map(enc, &mB2h, pw2h, HID, (uint64_t)NE*DIM, 64, 128);

    cudaFuncSetAttribute(gemm_tma<DIM, HID, true>,
                         cudaFuncAttributeMaxDynamicSharedMemorySize, SMEM_ASK);
    cudaFuncSetAttribute(gemm_tma<HID, DIM, false>,
                         cudaFuncAttributeMaxDynamicSharedMemorySize, SMEM_ASK);

    reset_kernel<<<1, 32>>>();
    router_kernel<<<NT / 8, 256>>>(x, Wr);
    offsets_kernel<<<1, 1>>>();
    scatter_kernel<<<(NT + 255) / 256, 256>>>();

    transpose_h_kernel<1><<<dim3(HID / 32, DIM / 32, NE), dim3(32, 8)>>>(W1);
    transpose_h_kernel<2><<<dim3(DIM / 32, HID / 32, NE), dim3(32, 8)>>>(W2);
    gather_h_kernel<<<NPAD, 128>>>(x);

    gemm_tma<DIM, HID, true><<<dim3(HID / 128, NPB), 512, SMEM_ASK>>>(b1, mA1h, mB1h);
    gemm_tma<HID, DIM, false><<<dim3(DIM / 128, NPB), 512, SMEM_ASK>>>(b2, mA2h, mB2h);

    combine_kernel<<<(int)((size_t)NT * DIM / 4 / 256), 256>>>(out);
    loss_kernel<<<1, 1>>>(out, out_size);
}

// round 17
// speedup vs baseline: 2.4823x; 1.0075x over previous
#include <cuda_runtime.h>
#include <cuda.h>
#include <cuda_fp16.h>
#include <math.h>
#include <stdint.h>

#define NT   16384
#define DIM  2048
#define HID  4096
#define NE   8
#define TK   2
#define NPAIR (NT*TK)
#define NPAD  (NPAIR + NE*256)     // 34816: per-expert 256-padded upper bound
#define NPB   (NPAD/256)

// ---------------- device scratch (no allocations allowed) ----------------
static __device__ __half g_w1h[(size_t)NE*HID*DIM];   // W1^T, fp16
static __device__ __half g_w2h[(size_t)NE*DIM*HID];   // W2^T, fp16
static __device__ __half g_xh[(size_t)NPAD*DIM];      // gathered x, fp16
static __device__ __half g_hh[(size_t)NPAD*HID];      // hidden, fp16
static __device__ float  g_o [(size_t)NPAD*DIM];
static __device__ int   g_top_idx[NPAIR];
static __device__ float g_top_w[NPAIR];
static __device__ int   g_ppos[NPAIR];
static __device__ int   g_perm[NPAD];
static __device__ int   g_counts[NE];
static __device__ int   g_poff[NE+1];
static __device__ int   g_cursor[NE];
static __device__ float g_probsum[NE];

// ---------------- helpers ----------------
__device__ __forceinline__ uint32_t smem_u32(const void* p) {
    uint32_t a;
    asm("{ .reg .u64 t; cvta.to.shared.u64 t, %1; cvt.u32.u64 %0, t; }" : "=r"(a) : "l"(p));
    return a;
}
#define SWZ128(o) ((o) ^ (((o) >> 3) & 0x70))

#define LDSM4(r, addr) \
    asm volatile("ldmatrix.sync.aligned.m8n8.x4.shared.b16 {%0,%1,%2,%3}, [%4];" \
        : "=r"((r)[0]), "=r"((r)[1]), "=r"((r)[2]), "=r"((r)[3]) : "r"(addr))

#define MMA_F16(d, a, bv0, bv1) \
    asm volatile("mma.sync.aligned.m16n8k16.row.col.f32.f16.f16.f32 " \
        "{%0,%1,%2,%3}, {%4,%5,%6,%7}, {%8,%9}, {%0,%1,%2,%3};" \
        : "+f"((d)[0]), "+f"((d)[1]), "+f"((d)[2]), "+f"((d)[3]) \
        : "r"((a)[0]), "r"((a)[1]), "r"((a)[2]), "r"((a)[3]), "r"(bv0), "r"(bv1))

#define TMA2D(smem, mapp, cx, cy, mbar) \
    asm volatile("cp.async.bulk.tensor.2d.shared::cta.global.tile.mbarrier::complete_tx::bytes " \
        "[%0], [%1, {%2, %3}], [%4];" \
        :: "r"(smem), "l"(mapp), "r"(cx), "r"(cy), "r"(mbar) : "memory")

#define MB_INIT(a, c) \
    asm volatile("mbarrier.init.shared.b64 [%0], %1;" :: "r"(a), "r"((uint32_t)(c)) : "memory")
#define MB_EXPECT(a, tx) \
    asm volatile("mbarrier.arrive.expect_tx.shared.b64 _, [%0], %1;" :: "r"(a), "r"((uint32_t)(tx)) : "memory")

__device__ __forceinline__ void mb_wait(uint32_t a, uint32_t parity) {
    asm volatile(
        "{\n\t.reg .pred P;\n"
        "W%=:\n\t"
        "mbarrier.try_wait.parity.acquire.cta.shared::cta.b64 P, [%0], %1, 0x989680;\n\t"
        "@P bra D%=;\n\t"
        "bra W%=;\n"
        "D%=:\n\t}"
        :: "r"(a), "r"(parity) : "memory");
}

// ---------------- reset ----------------
__global__ void reset_kernel() {
    int i = threadIdx.x;
    if (i < NE) { g_counts[i] = 0; g_cursor[i] = 0; g_probsum[i] = 0.f; }
}

// ---------------- router ----------------
__global__ __launch_bounds__(256) void router_kernel(const float* __restrict__ x,
                                                     const float* __restrict__ Wr) {
    __shared__ float s_ps[NE];
    __shared__ int   s_ct[NE];
    if (threadIdx.x < NE) { s_ps[threadIdx.x] = 0.f; s_ct[threadIdx.x] = 0; }
    __syncthreads();

    const int lane = threadIdx.x & 31;
    const int t    = blockIdx.x * 8 + (threadIdx.x >> 5);

    float accv[NE];
#pragma unroll
    for (int e = 0; e < NE; e++) accv[e] = 0.f;

    const float4* x4 = (const float4*)(x + (size_t)t * DIM);
    for (int d4 = lane; d4 < DIM / 4; d4 += 32) {
        float4 xv = x4[d4];
        float xs[4] = {xv.x, xv.y, xv.z, xv.w};
#pragma unroll
        for (int r = 0; r < 4; r++) {
            const float4* wr = (const float4*)(Wr + (size_t)(d4 * 4 + r) * NE);
            float4 a = wr[0], b = wr[1];
            accv[0] += xs[r] * a.x; accv[1] += xs[r] * a.y;
            accv[2] += xs[r] * a.z; accv[3] += xs[r] * a.w;
            accv[4] += xs[r] * b.x; accv[5] += xs[r] * b.y;
            accv[6] += xs[r] * b.z; accv[7] += xs[r] * b.w;
        }
    }
#pragma unroll
    for (int e = 0; e < NE; e++) {
#pragma unroll
        for (int o = 16; o > 0; o >>= 1)
            accv[e] += __shfl_down_sync(0xffffffffu, accv[e], o);
    }

    if (lane == 0) {
        float m = accv[0];
#pragma unroll
        for (int e = 1; e < NE; e++) m = fmaxf(m, accv[e]);
        float p[NE]; float s = 0.f;
#pragma unroll
        for (int e = 0; e < NE; e++) { p[e] = expf(accv[e] - m); s += p[e]; }
        float inv = 1.f / s;
#pragma unroll
        for (int e = 0; e < NE; e++) p[e] *= inv;

        int i0 = 0;
#pragma unroll
        for (int e = 1; e < NE; e++) if (p[e] > p[i0]) i0 = e;
        int i1 = (i0 == 0) ? 1 : 0;
#pragma unroll
        for (int e = 0; e < NE; e++) if (e != i0 && p[e] > p[i1]) i1 = e;

        float ws = p[i0] + p[i1];
        g_top_idx[t * 2 + 0] = i0;  g_top_idx[t * 2 + 1] = i1;
        g_top_w[t * 2 + 0] = p[i0] / ws;  g_top_w[t * 2 + 1] = p[i1] / ws;

#pragma unroll
        for (int e = 0; e < NE; e++) atomicAdd(&s_ps[e], p[e]);
        atomicAdd(&s_ct[i0], 1);
        atomicAdd(&s_ct[i1], 1);
    }
    __syncthreads();
    if (threadIdx.x < NE) {
        atomicAdd(&g_probsum[threadIdx.x], s_ps[threadIdx.x]);
        atomicAdd(&g_counts[threadIdx.x],  s_ct[threadIdx.x]);
    }
}

// ---------------- padded prefix offsets (256-multiples for M=256 tiles) ----------------
__global__ void offsets_kernel() {
    if (threadIdx.x == 0) {
        int s = 0;
        for (int e = 0; e < NE; e++) {
            g_poff[e] = s;
            s += ((g_counts[e] + 255) / 256) * 256;
        }
        g_poff[NE] = s;
    }
}

// ---------------- scatter into padded per-expert segments ----------------
__global__ void scatter_kernel() {
    int t = blockIdx.x * blockDim.x + threadIdx.x;
    if (t >= NT) return;
#pragma unroll
    for (int k = 0; k < TK; k++) {
        int e = g_top_idx[t * 2 + k];
        int pos = g_poff[e] + atomicAdd(&g_cursor[e], 1);
        g_perm[pos] = t;
        g_ppos[t * 2 + k] = pos;
    }
}

// ---------------- transpose + fp16 round of expert weights ----------------
template<int WHICH>   // 1: W1 [DIM][HID] -> [HID][DIM] ; 2: W2 [HID][DIM] -> [DIM][HID]
__global__ void transpose_h_kernel(const float* __restrict__ src) {
    constexpr int R = (WHICH == 1) ? DIM : HID;
    constexpr int C = (WHICH == 1) ? HID : DIM;
    __half* dh = (WHICH == 1) ? g_w1h : g_w2h;

    __shared__ float tile[32][33];
    int e = blockIdx.z;
    const float* s = src + (size_t)e * R * C;
    __half* ph = dh + (size_t)e * R * C;
    int c0 = blockIdx.x * 32, r0 = blockIdx.y * 32;

    for (int i = threadIdx.y; i < 32; i += 8)
        tile[i][threadIdx.x] = s[(size_t)(r0 + i) * C + c0 + threadIdx.x];
    __syncthreads();
    for (int i = threadIdx.y; i < 32; i += 8) {
        float v = tile[threadIdx.x][i];
        ph[(size_t)(c0 + i) * R + r0 + threadIdx.x] = __float2half(v);
    }
}

// ---------------- gather tokens + fp16 round ----------------
__global__ __launch_bounds__(128) void gather_h_kernel(const float* __restrict__ x) {
    int p = blockIdx.x;
    if (p >= g_poff[NE]) return;
    int e = 0;
    while (p >= g_poff[e + 1]) e++;
    int local = p - g_poff[e];
    __half* ph = g_xh + (size_t)p * DIM;
    if (local >= g_counts[e]) {
        for (int c = threadIdx.x; c < DIM / 2; c += 128)
            ((uint32_t*)ph)[c] = 0u;
        return;
    }
    int tok = g_perm[p];
    const float4* xs = (const float4*)(x + (size_t)tok * DIM);
    for (int c4 = threadIdx.x; c4 < DIM / 4; c4 += 128) {
        float4 v = xs[c4];
        ((__half2*)ph)[c4 * 2 + 0] = __halves2half2(__float2half(v.x), __float2half(v.y));
        ((__half2*)ph)[c4 * 2 + 1] = __halves2half2(__float2half(v.z), __float2half(v.w));
    }
}

// ---------------- Persistent TMA-fed HMMA grouped GEMM ----------------
// Persistent CTAs (grid = #SMs). Each CTA loops tiles (stride gridDim.x) with a
// SINGLE continuous 3-stage k-block pipeline whose refills cross tile boundaries:
// prologue fill happens once per kernel, epilogues overlap next tile's loads.
// Tile: M=256 x N=128, 512 threads. K-chunk 64 (128B rows, SW128 via TMA).
#define A_PL   32768                 // 256 rows x 128B
#define B_PL   16384                 // 128 rows x 128B
#define STAGE_B (A_PL + B_PL)        // 49152
#define NSTG    3
#define SMEM_ASK (1024 + 1024 + NSTG*STAGE_B)

template<int KTOT, int NTOT, bool GELU1>
__global__ __launch_bounds__(512, 1) void gemm_tma(
    const float* __restrict__ bias_base,
    const __grid_constant__ CUtensorMap mAh,
    const __grid_constant__ CUtensorMap mBh) {

    constexpr int NIT   = KTOT / 64;
    constexpr int NCOLT = NTOT / 128;

    const int tid = threadIdx.x, wid = tid >> 5, lane = tid & 31;
    const int wm = (wid & 7) * 32, wn = (wid >> 3) * 64;
    const int bidx = blockIdx.x, gdim = gridDim.x;

    extern __shared__ char smem[];
    const uint32_t sb0 = (smem_u32(smem) + 1023) & ~1023u;
    const uint32_t data0 = sb0 + 1024;

    if (tid == 0) {
#pragma unroll
        for (int s = 0; s < NSTG; s++) MB_INIT(sb0 + 8*s, 1);
    }
    __syncthreads();

    const int rows_active = g_poff[NE] >> 8;       // /256
    const int ntiles = rows_active * NCOLT;

    // refill local k-block kb (this CTA's stream) into stage stg_r
    auto refill = [&](int kb, int stg_r) {
        const int lt = kb / NIT;
        const int t2 = bidx + lt * gdim;
        if (t2 >= ntiles) return;
        const int kk   = kb % NIT;
        const int rowb = (t2 / NCOLT) * 256;
        const int colb = (t2 % NCOLT) * 128;
        int ee = 0;
        while (rowb >= g_poff[ee + 1]) ee++;
        const uint32_t st = data0 + stg_r * STAGE_B;
        const uint32_t mbar = sb0 + 8 * stg_r;
        MB_EXPECT(mbar, STAGE_B);
        TMA2D(st,        &mAh, kk * 64, rowb, mbar);
        TMA2D(st + A_PL, &mBh, kk * 64, ee * NTOT + colb, mbar);
    };

    if (tid == 0) { refill(0, 0); refill(1, 1); refill(2, 2); }

    // per-lane ldmatrix address components
    const int arow = lane & 15;
    const int akb  = lane >> 4;
    const int nrow = ((lane >> 4) << 3) + (lane & 7);
    const int bkb  = (lane >> 3) & 1;

    const int gid = lane >> 2, tig = lane & 3;

    int stg = 0, par = 0, nk = 3;   // consumer stage/parity, next refill kb

    for (int i = 0; ; i++) {
        const int t = bidx + i * gdim;
        if (t >= ntiles) break;
        const int rowbase = (t / NCOLT) * 256;
        const int colbase = (t % NCOLT) * 128;
        int e = 0;
        while (rowbase >= g_poff[e + 1]) e++;

        float acc[2][8][4];
#pragma unroll
        for (int mt = 0; mt < 2; mt++)
#pragma unroll
            for (int nt = 0; nt < 8; nt++)
#pragma unroll
                for (int r = 0; r < 4; r++) acc[mt][nt][r] = 0.f;

        for (int it = 0; it < NIT; ++it) {
            const uint32_t base = data0 + stg * STAGE_B;
            mb_wait(sb0 + 8 * stg, par);

            const uint32_t bAh = base, bBh = base + A_PL;

#pragma unroll
            for (int ks = 0; ks < 4; ks++) {
                const int kb0 = ks * 2;
                uint32_t a_hi[2][4];
#pragma unroll
                for (int mt = 0; mt < 2; mt++) {
                    uint32_t off = SWZ128((uint32_t)((wm + mt*16 + arow) * 128 + (kb0 + akb) * 16));
                    LDSM4(a_hi[mt], bAh + off);
                }
#pragma unroll
                for (int np = 0; np < 4; np++) {
                    uint32_t boff = SWZ128((uint32_t)((wn + np*16 + nrow) * 128 + (kb0 + bkb) * 16));
                    uint32_t b_hi[4];
                    LDSM4(b_hi, bBh + boff);
#pragma unroll
                    for (int mt = 0; mt < 2; mt++) {
                        MMA_F16(acc[mt][np*2+0], a_hi[mt], b_hi[0], b_hi[1]);
                        MMA_F16(acc[mt][np*2+1], a_hi[mt], b_hi[2], b_hi[3]);
                    }
                }
            }
            __syncthreads();
            if (tid == 0) refill(nk, stg);   // stage just freed by the sync
            nk++;
            if (++stg == NSTG) { stg = 0; par ^= 1; }
        }

        // ---- epilogue for tile t (next tile's TMA loads stream in meanwhile) ----
        const float* bp = bias_base + (size_t)e * NTOT + colbase + wn;

#pragma unroll
        for (int mt = 0; mt < 2; mt++) {
#pragma unroll
            for (int half = 0; half < 2; half++) {
                const int m = rowbase + wm + mt*16 + gid + half*8;
                if (GELU1) {
                    __half* ph = g_hh + (size_t)m * HID + colbase + wn;
#pragma unroll
                    for (int nt = 0; nt < 8; nt++) {
                        int c = nt*8 + tig*2;
                        float v0 = acc[mt][nt][half*2+0] + bp[c];
                        float v1 = acc[mt][nt][half*2+1] + bp[c+1];
                        float gg0 = 0.5f * v0 * (1.f + erff(v0 * 0.70710678118654752440f));
                        float gg1 = 0.5f * v1 * (1.f + erff(v1 * 0.70710678118654752440f));
                        *(__half2*)(ph + c) = __halves2half2(__float2half(gg0), __float2half(gg1));
                    }
                } else {
                    float* po = g_o + (size_t)m * DIM + colbase + wn;
#pragma unroll
                    for (int nt = 0; nt < 8; nt++) {
                        int c = nt*8 + tig*2;
                        float2 v;
                        v.x = acc[mt][nt][half*2+0] + bp[c];
                        v.y = acc[mt][nt][half*2+1] + bp[c+1];
                        *(float2*)(po + c) = v;
                    }
                }
            }
        }
    }
}

// ---------------- combine two expert contributions per token ----------------
__global__ __launch_bounds__(256) void combine_kernel(float* __restrict__ out) {
    size_t id = (size_t)blockIdx.x * 256 + threadIdx.x;
    int t = (int)(id / (DIM / 4));
    int c = (int)(id % (DIM / 4));
    int p0 = g_ppos[t * 2 + 0], p1 = g_ppos[t * 2 + 1];
    float w0 = g_top_w[t * 2 + 0], w1 = g_top_w[t * 2 + 1];
    float4 a = ((const float4*)(g_o + (size_t)p0 * DIM))[c];
    float4 b = ((const float4*)(g_o + (size_t)p1 * DIM))[c];
    float4 r;
    r.x = w0 * a.x + w1 * b.x;
    r.y = w0 * a.y + w1 * b.y;
    r.z = w0 * a.z + w1 * b.z;
    r.w = w0 * a.w + w1 * b.w;
    ((float4*)(out + (size_t)t * DIM))[c] = r;
}

// ---------------- load-balance loss ----------------
__global__ void loss_kernel(float* __restrict__ out, int out_size) {
    if (out_size > NT * DIM) {
        float loss = 0.f;
        for (int e = 0; e < NE; e++)
            loss += (g_probsum[e] / (float)NT) * ((float)g_counts[e] / (float)(NT * TK));
        out[(size_t)NT * DIM] = loss * (float)NE;
    }
}

// ---------------- host: tensor-map construction ----------------
typedef CUresult (*PFN_tmEncode)(CUtensorMap*, CUtensorMapDataType, cuuint32_t, void*,
                                 const cuuint64_t*, const cuuint64_t*, const cuuint32_t*,
                                 const cuuint32_t*, CUtensorMapInterleave, CUtensorMapSwizzle,
                                 CUtensorMapL2promotion, CUtensorMapFloatOOBfill);

static void make_map(PFN_tmEncode enc, CUtensorMap* m, void* base,
                     uint64_t d0, uint64_t d1, uint32_t b0, uint32_t b1) {
    cuuint64_t dims[2]    = {d0, d1};
    cuuint64_t strides[1] = {d0 * 2};
    cuuint32_t box[2]     = {b0, b1};
    cuuint32_t es[2]      = {1, 1};
    enc(m, CU_TENSOR_MAP_DATA_TYPE_FLOAT16, 2, base, dims, strides, box, es,
        CU_TENSOR_MAP_INTERLEAVE_NONE, CU_TENSOR_MAP_SWIZZLE_128B,
        CU_TENSOR_MAP_L2_PROMOTION_L2_128B, CU_TENSOR_MAP_FLOAT_OOB_FILL_NONE);
}

// ---------------- launch ----------------
extern "C" void kernel_launch(void* const* d_in, const int* in_sizes, int n_in,
                              void* d_out, int out_size) {
    const float* x  = (const float*)d_in[0];
    const float* Wr = (const float*)d_in[1];
    const float* W1 = (const float*)d_in[2];
    const float* b1 = (const float*)d_in[3];
    const float* W2 = (const float*)d_in[4];
    const float* b2 = (const float*)d_in[5];
    float* out = (float*)d_out;

    void* pfn = nullptr;
    cudaDriverEntryPointQueryResult qr;
    cudaGetDriverEntryPoint("cuTensorMapEncodeTiled", &pfn, cudaEnableDefault, &qr);
    PFN_tmEncode enc = (PFN_tmEncode)pfn;

    void *pxh, *phh, *pw1h, *pw2h;
    cudaGetSymbolAddress(&pxh,  g_xh);
    cudaGetSymbolAddress(&phh,  g_hh);
    cudaGetSymbolAddress(&pw1h, g_w1h); cudaGetSymbolAddress(&pw2h, g_w2h);

    CUtensorMap mA1h, mB1h, mA2h, mB2h;
    make_map(enc, &mA1h, pxh,  DIM, NPAD,             64, 256);
    make_map(enc, &mB1h, pw1h, DIM, (uint64_t)NE*HID, 64, 128);
    make_map(enc, &mA2h, phh,  HID, NPAD,             64, 256);
    make_map(enc, &mB2h, pw2h, HID, (uint64_t)NE*DIM, 64, 128);

    cudaFuncSetAttribute(gemm_tma<DIM, HID, true>,
                         cudaFuncAttributeMaxDynamicSharedMemorySize, SMEM_ASK);
    cudaFuncSetAttribute(gemm_tma<HID, DIM, false>,
                         cudaFuncAttributeMaxDynamicSharedMemorySize, SMEM_ASK);

    int dev = 0, nsm = 148;
    cudaGetDevice(&dev);
    cudaDeviceGetAttribute(&nsm, cudaDevAttrMultiProcessorCount, dev);

    reset_kernel<<<1, 32>>>();
    router_kernel<<<NT / 8, 256>>>(x, Wr);
    offsets_kernel<<<1, 1>>>();
    scatter_kernel<<<(NT + 255) / 256, 256>>>();

    transpose_h_kernel<1><<<dim3(HID / 32, DIM / 32, NE), dim3(32, 8)>>>(W1);
    transpose_h_kernel<2><<<dim3(DIM / 32, HID / 32, NE), dim3(32, 8)>>>(W2);
    gather_h_kernel<<<NPAD, 128>>>(x);

    gemm_tma<DIM, HID, true><<<nsm, 512, SMEM_ASK>>>(b1, mA1h, mB1h);
    gemm_tma<HID, DIM, false><<<nsm, 512, SMEM_ASK>>>(b2, mA2h, mB2h);

    combine_kernel<<<(int)((size_t)NT * DIM / 4 / 256), 256>>>(out);
    loss_kernel<<<1, 1>>>(out, out_size);
}